// round 14
// baseline (speedup 1.0000x reference)
#include <cuda_runtime.h>

// RoI bilinear pooling:
//   feat: (1, H=200, W=200, C=1024) fp32
//   rois: (N=300, 4) int32  [x0, y0, w, h]
//   out : (N, 7, 7, C) fp32
//
// R14: R13 champion (2 cells/CTA, straight-line burst-8 LDG.128, occ-8,
// weight-zero pointer-redirect dedup, lerp-form fma, __stcs) + ALU trim:
// all addressing in 32-bit float4-granule offsets (max ~10.2M << 2^32),
// and the hasB tail branch removed (last pair writes cell 48 twice with
// identical data — deterministic). Kernel sits on the B300 LTS cap
// (~11.6 TB/s); remaining levers are instruction count / clock headroom.

#define POOL  7
#define FH    200
#define FW    200
#define FC    1024
#define VEC   (FC / 4)     // 256 float4 per pixel row
#define NCELL (POOL * POOL)
#define NPAIR ((NCELL + 1) / 2)   // 25

// 32-bit float4-granule offset of pixel (iy, ix)
__device__ __forceinline__ unsigned pix_off(int iy, int ix) {
    return (unsigned)(iy * FW + ix) * (unsigned)VEC;
}

__device__ __forceinline__ void cell_setup(int cell, int x0, int y0, int w, int h,
                                           unsigned* o00, unsigned* o01,
                                           unsigned* o10, unsigned* o11,
                                           float* fx, float* fy)
{
    const int py = cell / POOL;
    const int px = cell - py * POOL;

    const float ry = (float)py * ((float)h / (float)POOL);
    const float rx = (float)px * ((float)w / (float)POOL);
    const int ylo = (int)floorf(ry);
    const int xlo = (int)floorf(rx);
    float ffy = ry - (float)ylo;
    float ffx = rx - (float)xlo;
    const int yhi = min(ylo + 1, h - 1);
    const int xhi = min(xlo + 1, w - 1);

    const int iy0 = min(max(y0 + ylo, 0), FH - 1);
    int       iy1 = min(max(y0 + yhi, 0), FH - 1);
    const int ix0 = min(max(x0 + xlo, 0), FW - 1);
    int       ix1 = min(max(x0 + xhi, 0), FW - 1);

    // Clamp-duplicates carry identical data -> weight fold to 0 is exact.
    if (ix1 == ix0) ffx = 0.0f;
    if (iy1 == iy0) ffy = 0.0f;
    // Weight-zero rows: redirect to the already-loaded row (SEL, no branch).
    // Duplicate-address loads merge in L1 -> no extra LTS traffic.
    ix1 = (ffx == 0.0f) ? ix0 : ix1;
    iy1 = (ffy == 0.0f) ? iy0 : iy1;

    *fx = ffx;
    *fy = ffy;

    *o00 = pix_off(iy0, ix0);
    *o01 = pix_off(iy0, ix1);
    *o10 = pix_off(iy1, ix0);
    *o11 = pix_off(iy1, ix1);
}

// bilinear via lerp form: fma(f, b-a, a); exact pass-through when f==0.
__device__ __forceinline__ float4 bilerp(float4 a, float4 b, float4 g, float4 d,
                                         float fx, float fy)
{
    float4 t, u, o;
    t.x = fmaf(fx, b.x - a.x, a.x);
    t.y = fmaf(fx, b.y - a.y, a.y);
    t.z = fmaf(fx, b.z - a.z, a.z);
    t.w = fmaf(fx, b.w - a.w, a.w);
    u.x = fmaf(fx, d.x - g.x, g.x);
    u.y = fmaf(fx, d.y - g.y, g.y);
    u.z = fmaf(fx, d.z - g.z, g.z);
    u.w = fmaf(fx, d.w - g.w, g.w);
    o.x = fmaf(fy, u.x - t.x, t.x);
    o.y = fmaf(fy, u.y - t.y, t.y);
    o.z = fmaf(fy, u.z - t.z, t.z);
    o.w = fmaf(fy, u.w - t.w, t.w);
    return o;
}

__global__ __launch_bounds__(VEC, 8)
void roi_pool_kernel(const float* __restrict__ feat,
                     const int*   __restrict__ rois,
                     float*       __restrict__ out)
{
    const int pair = blockIdx.x;            // 0..24
    const int n    = blockIdx.y;            // roi index
    const int cellA = pair * 2;
    const int cellB = min(cellA + 1, NCELL - 1);  // last pair: B==A (benign dup store)

    const int4 r = __ldg(((const int4*)rois) + n);
    const int x0 = r.x, y0 = r.y, w = r.z, h = r.w;

    unsigned a00, a01, a10, a11;
    unsigned b00, b01, b10, b11;
    float afx, afy, bfx, bfy;

    cell_setup(cellA, x0, y0, w, h, &a00, &a01, &a10, &a11, &afx, &afy);
    cell_setup(cellB, x0, y0, w, h, &b00, &b01, &b10, &b11, &bfx, &bfy);

    const unsigned c = threadIdx.x;         // 0..255 float4 lanes
    const float4* fv = (const float4*)feat;

    // Straight-line burst: all 8 loads unconditional, front-batched.
    const float4 va = __ldg(fv + a00 + c);
    const float4 vb = __ldg(fv + a01 + c);
    const float4 vg = __ldg(fv + a10 + c);
    const float4 vd = __ldg(fv + a11 + c);
    const float4 ua = __ldg(fv + b00 + c);
    const float4 ub = __ldg(fv + b01 + c);
    const float4 ug = __ldg(fv + b10 + c);
    const float4 ud = __ldg(fv + b11 + c);

    float4* outv = (float4*)out;
    const unsigned base = (unsigned)(n * NCELL) * VEC;  // max ~3.76M float4 ✓

    // Streaming stores: output is write-once, keep L2 for feat.
    __stcs(outv + base + (unsigned)cellA * VEC + c, bilerp(va, vb, vg, vd, afx, afy));
    __stcs(outv + base + (unsigned)cellB * VEC + c, bilerp(ua, ub, ug, ud, bfx, bfy));
}

extern "C" void kernel_launch(void* const* d_in, const int* in_sizes, int n_in,
                              void* d_out, int out_size)
{
    const float* feat = (const float*)d_in[0];   // (1,200,200,1024) fp32
    const int*   rois = (const int*)d_in[1];     // (N,4) int32
    const int N = in_sizes[1] / 4;

    dim3 grid(NPAIR, N);
    roi_pool_kernel<<<grid, VEC>>>(feat, rois, (float*)d_out);
}

// round 16
// speedup vs baseline: 1.0920x; 1.0920x over previous
#include <cuda_runtime.h>

// RoI bilinear pooling:
//   feat: (1, H=200, W=200, C=1024) fp32
//   rois: (N=300, 4) int32  [x0, y0, w, h]
//   out : (N, 7, 7, C) fp32
//
// R15 = R13 champion, reverted after R14's addressing change collapsed the
// load burst (IMAD.WIDE per LDG serialized the MLP). Final form:
//   - 2 cells/CTA, 7500 CTAs, straight-line burst-8 LDG.128 (64-bit base
//     pointers computed once in setup; loads are [ptr + c*16] form),
//   - weight-zero pointer-redirect dedup (SEL, zero branches): rows with
//     bilinear weight exactly 0 (px==0/py==0 or clamp-duplicates folded to
//     fx/fy:=0) alias the already-loaded row and merge in L1 -> no LTS bytes,
//   - lerp-form fma bilinear (exact pass-through at f==0),
//   - __stcs streaming stores (write-once output).
// Measured at the B300 LTS throughput cap (~11.6 TB/s L2<->SM).

#define POOL  7
#define FH    200
#define FW    200
#define FC    1024
#define VEC   (FC / 4)     // 256 float4 per pixel row
#define NCELL (POOL * POOL)
#define NPAIR ((NCELL + 1) / 2)   // 25

__device__ __forceinline__ void cell_setup(int cell, int x0, int y0, int w, int h,
                                           const float* __restrict__ feat,
                                           const float4** p00, const float4** p01,
                                           const float4** p10, const float4** p11,
                                           float* fx, float* fy)
{
    const int py = cell / POOL;
    const int px = cell - py * POOL;

    const float ry = (float)py * ((float)h / (float)POOL);
    const float rx = (float)px * ((float)w / (float)POOL);
    const int ylo = (int)floorf(ry);
    const int xlo = (int)floorf(rx);
    float ffy = ry - (float)ylo;
    float ffx = rx - (float)xlo;
    const int yhi = min(ylo + 1, h - 1);
    const int xhi = min(xlo + 1, w - 1);

    const int iy0 = min(max(y0 + ylo, 0), FH - 1);
    int       iy1 = min(max(y0 + yhi, 0), FH - 1);
    const int ix0 = min(max(x0 + xlo, 0), FW - 1);
    int       ix1 = min(max(x0 + xhi, 0), FW - 1);

    // Clamp-duplicates carry identical data -> weight fold to 0 is exact.
    if (ix1 == ix0) ffx = 0.0f;
    if (iy1 == iy0) ffy = 0.0f;
    // Weight-zero rows: redirect pointer to the already-loaded row (SEL, no
    // branch). Duplicate-address loads merge in L1 -> no extra L2 traffic.
    ix1 = (ffx == 0.0f) ? ix0 : ix1;
    iy1 = (ffy == 0.0f) ? iy0 : iy1;

    *fx = ffx;
    *fy = ffy;

    *p00 = (const float4*)(feat + ((size_t)iy0 * FW + ix0) * FC);
    *p01 = (const float4*)(feat + ((size_t)iy0 * FW + ix1) * FC);
    *p10 = (const float4*)(feat + ((size_t)iy1 * FW + ix0) * FC);
    *p11 = (const float4*)(feat + ((size_t)iy1 * FW + ix1) * FC);
}

// bilinear via lerp form: fma(f, b-a, a); exact pass-through when f==0.
__device__ __forceinline__ float4 bilerp(float4 a, float4 b, float4 g, float4 d,
                                         float fx, float fy)
{
    float4 t, u, o;
    t.x = fmaf(fx, b.x - a.x, a.x);
    t.y = fmaf(fx, b.y - a.y, a.y);
    t.z = fmaf(fx, b.z - a.z, a.z);
    t.w = fmaf(fx, b.w - a.w, a.w);
    u.x = fmaf(fx, d.x - g.x, g.x);
    u.y = fmaf(fx, d.y - g.y, g.y);
    u.z = fmaf(fx, d.z - g.z, g.z);
    u.w = fmaf(fx, d.w - g.w, g.w);
    o.x = fmaf(fy, u.x - t.x, t.x);
    o.y = fmaf(fy, u.y - t.y, t.y);
    o.z = fmaf(fy, u.z - t.z, t.z);
    o.w = fmaf(fy, u.w - t.w, t.w);
    return o;
}

__global__ __launch_bounds__(VEC, 8)
void roi_pool_kernel(const float* __restrict__ feat,
                     const int*   __restrict__ rois,
                     float*       __restrict__ out)
{
    const int pair = blockIdx.x;            // 0..24
    const int n    = blockIdx.y;            // roi index
    const int cellA = pair * 2;
    const bool hasB = (cellA + 1) < NCELL;
    const int cellB = hasB ? (cellA + 1) : cellA;

    const int4 r = __ldg(((const int4*)rois) + n);
    const int x0 = r.x, y0 = r.y, w = r.z, h = r.w;

    const float4 *a00, *a01, *a10, *a11;
    const float4 *b00, *b01, *b10, *b11;
    float afx, afy, bfx, bfy;

    cell_setup(cellA, x0, y0, w, h, feat, &a00, &a01, &a10, &a11, &afx, &afy);
    cell_setup(cellB, x0, y0, w, h, feat, &b00, &b01, &b10, &b11, &bfx, &bfy);

    const int c = threadIdx.x;              // 0..255 float4 lanes

    // Straight-line burst: all 8 loads unconditional, front-batched.
    const float4 va = __ldg(a00 + c);
    const float4 vb = __ldg(a01 + c);
    const float4 vg = __ldg(a10 + c);
    const float4 vd = __ldg(a11 + c);
    const float4 ua = __ldg(b00 + c);
    const float4 ub = __ldg(b01 + c);
    const float4 ug = __ldg(b10 + c);
    const float4 ud = __ldg(b11 + c);

    float4* outv = (float4*)out;
    const size_t base = (size_t)n * NCELL;

    // Streaming stores: output is write-once, keep L2 for feat.
    __stcs(outv + (base + cellA) * VEC + c, bilerp(va, vb, vg, vd, afx, afy));

    if (hasB) {
        __stcs(outv + (base + cellB) * VEC + c, bilerp(ua, ub, ug, ud, bfx, bfy));
    }
}

extern "C" void kernel_launch(void* const* d_in, const int* in_sizes, int n_in,
                              void* d_out, int out_size)
{
    const float* feat = (const float*)d_in[0];   // (1,200,200,1024) fp32
    const int*   rois = (const int*)d_in[1];     // (N,4) int32
    const int N = in_sizes[1] / 4;

    dim3 grid(NPAIR, N);
    roi_pool_kernel<<<grid, VEC>>>(feat, rois, (float*)d_out);
}